// round 11
// baseline (speedup 1.0000x reference)
#include <cuda_runtime.h>
#include <cuda_fp16.h>
#include <cstdint>
#include <math.h>

#define TT 4096      // SEQ_LEN (M for both GEMMs)
#define HH 2048      // D_HIDDEN
#define DM 4096      // D_MODEL
#define KK 4096      // K for both GEMMs
#define NN 4096      // N for both GEMMs
#define NCHUNK 64
#define CLEN 64

#define BM 128
#define BN 128
#define BK 128               // two 64-wide k-halves per chunk
#define KC (KK / BK)         // 32 chunks
#define NTILE ((TT / BM) * (NN / BN))   // 1024
#define GRID_P 148           // persistent CTAs
#define STG_B 0x10000        // 64KB per stage
#define SMEM_TOT (2 * STG_B) // 128KB

// ---------------- device scratch (no allocations allowed) ----------------
__device__ __half g_x_h[(size_t)TT * DM];     // x fp16
__device__ __half g_b_h[(size_t)NN * KK];     // [gB_re; gB_im] fp16
__device__ __half g_c_h[(size_t)NN * KK];     // [C_re | -C_im] fp16
__device__ __half g_h_h[(size_t)TT * KK];     // hidden (re|im) fp16
__device__ __half g_bu_h[(size_t)TT * NN];    // Bu (re|im) fp16
__device__ float g_lam_re[HH], g_lam_im[HH];
__device__ float g_lamL_re[HH], g_lamL_im[HH];
__device__ float g_gam[HH];
__device__ float g_chunk_re[NCHUNK * HH], g_chunk_im[NCHUNK * HH];
__device__ float g_carry_re[NCHUNK * HH], g_carry_im[NCHUNK * HH];

// ---------------- helpers ----------------
__device__ __forceinline__ uint32_t smem_u32(const void* p) {
    uint32_t a;
    asm("{ .reg .u64 t; cvta.to.shared.u64 t, %1; cvt.u32.u64 %0, t; }" : "=r"(a) : "l"(p));
    return a;
}
#define SWZ(o) ((o) ^ (((o) >> 3) & 0x70))

__device__ __forceinline__ void cpasync16(uint32_t dst, const void* src) {
    asm volatile("cp.async.cg.shared.global [%0], [%1], 16;" :: "r"(dst), "l"(src));
}
__device__ __forceinline__ void ldsm4(uint32_t* r, uint32_t addr) {
    asm volatile("ldmatrix.sync.aligned.m8n8.x4.shared.b16 {%0,%1,%2,%3}, [%4];"
                 : "=r"(r[0]), "=r"(r[1]), "=r"(r[2]), "=r"(r[3]) : "r"(addr));
}
__device__ __forceinline__ void mma16816(float* c, const uint32_t* a,
                                         uint32_t b0, uint32_t b1) {
    asm volatile(
        "mma.sync.aligned.m16n8k16.row.col.f32.f16.f16.f32 "
        "{%0,%1,%2,%3}, {%4,%5,%6,%7}, {%8,%9}, {%0,%1,%2,%3};"
        : "+f"(c[0]), "+f"(c[1]), "+f"(c[2]), "+f"(c[3])
        : "r"(a[0]), "r"(a[1]), "r"(a[2]), "r"(a[3]), "r"(b0), "r"(b1));
}

// pack 4 floats -> fp16 (uint2), packed cvt
__device__ __forceinline__ uint2 pack4s(const float4 v) {
    __half2 p0 = __floats2half2_rn(v.x, v.y);
    __half2 p1 = __floats2half2_rn(v.z, v.w);
    uint2 r;
    r.x = *(uint32_t*)&p0; r.y = *(uint32_t*)&p1;
    return r;
}

// ---------------- param precompute ----------------
__global__ void init_params(const float* __restrict__ nu_log,
                            const float* __restrict__ theta_log,
                            const float* __restrict__ gamma_log) {
    int h = blockIdx.x * blockDim.x + threadIdx.x;
    if (h >= HH) return;
    float nu = expf(nu_log[h]);
    float th = expf(theta_log[h]);
    float mag = expf(-nu);
    float lr = mag * cosf(th), li = mag * sinf(th);
    g_lam_re[h] = lr; g_lam_im[h] = li;
    g_gam[h] = expf(gamma_log[h]);
    float ar = 1.f, ai = 0.f;
    for (int i = 0; i < CLEN; i++) {
        float nr = ar * lr - ai * li;
        ai = ar * li + ai * lr; ar = nr;
    }
    g_lamL_re[h] = ar; g_lamL_im[h] = ai;
}

// ---------------- conversions for x and B' (needed before GEMM1) ----------------
#define NBREG ((size_t)TT * DM / 8 / 256)   // 8192 blocks per region
__global__ void conv_xb(const float* __restrict__ x,
                        const float* __restrict__ Bre, const float* __restrict__ Bim) {
    unsigned bid = blockIdx.x;
    if (bid < NBREG) {
        size_t i = ((size_t)bid * 256 + threadIdx.x) * 8;
        float4 v0 = *(const float4*)(x + i);
        float4 v1 = *(const float4*)(x + i + 4);
        uint2 a = pack4s(v0), b = pack4s(v1);
        *(uint4*)(g_x_h + i) = make_uint4(a.x, a.y, b.x, b.y);
    } else {
        size_t i = ((size_t)(bid - NBREG) * 256 + threadIdx.x) * 8;
        unsigned row = (unsigned)(i >> 12);
        const float* src = (row < HH) ? (Bre + i) : (Bim + (i - (size_t)HH * DM));
        float g = g_gam[row < HH ? row : row - HH];
        float4 v0 = *(const float4*)src;
        float4 v1 = *(const float4*)(src + 4);
        v0.x *= g; v0.y *= g; v0.z *= g; v0.w *= g;
        v1.x *= g; v1.y *= g; v1.z *= g; v1.w *= g;
        uint2 a = pack4s(v0), b = pack4s(v1);
        *(uint4*)(g_b_h + i) = make_uint4(a.x, a.y, b.x, b.y);
    }
}

// ---------------- persistent fp16 GEMM, 128x128 tiles, BK=128 ----------------
// MODE 0: g_bu_h = fp16( x @ B'^T ); ALSO converts C' (interleaved side-work)
// MODE 1: out    = h @ C'^T + x*D   (fp32 out)
template <int MODE>
__global__ __launch_bounds__(256, 1) void gemm_split(
    const float* __restrict__ x, const float* __restrict__ Dvec, float* __restrict__ out,
    const float* __restrict__ Cre, const float* __restrict__ Cim)
{
    extern __shared__ char smem[];
    const uint32_t sb = smem_u32(smem);
    const __half *Ah, *Bh;
    if (MODE == 0) { Ah = g_x_h; Bh = g_b_h; }
    else           { Ah = g_h_h; Bh = g_c_h; }

    const int tid = threadIdx.x, lane = tid & 31, wid = tid >> 5;
    const int wm = wid & 1, wn = wid >> 1;           // 2 x 4 warp grid -> 64x32 warp tile
    const int tile0 = blockIdx.x;
    const int ntiles = (NTILE - 1 - tile0) / GRID_P + 1;
    const long Gtot = (long)ntiles * KC;

    // --- interleaved C' conversion state (MODE 0, warps 0-1 only) ---
    // Global (tile, chunk) pairs number 1024*32 = 32768; x64 octs x8 elems
    // = 16.78M = |C'| exactly: each chunk-iteration owns 64 octs.
    const bool doconv = (MODE == 0) && (tid < 64);
    float4 cv0, cv1;
    auto conv_load = [&](long gq) {
        size_t i = ((size_t)gq * 64 + tid) * 8;
        unsigned d = (unsigned)(i >> 12);
        unsigned jj = (unsigned)(i & (KK - 1));
        const float* src = (jj < HH) ? (Cre + (size_t)d * HH + jj)
                                     : (Cim + (size_t)d * HH + (jj - HH));
        cv0 = *(const float4*)src;
        cv1 = *(const float4*)(src + 4);
    };
    auto conv_store = [&](long gq) {
        size_t i = ((size_t)gq * 64 + tid) * 8;
        unsigned jj = (unsigned)(i & (KK - 1));
        float4 v0 = cv0, v1 = cv1;
        if (jj >= HH) {
            v0.x = -v0.x; v0.y = -v0.y; v0.z = -v0.z; v0.w = -v0.w;
            v1.x = -v1.x; v1.y = -v1.y; v1.z = -v1.z; v1.w = -v1.w;
        }
        uint2 a = pack4s(v0), b = pack4s(v1);
        *(uint4*)(g_c_h + i) = make_uint4(a.x, a.y, b.x, b.y);
    };

    // stage layout (64KB): A half0 0x0000, A half1 0x4000, B half0 0x8000, B half1 0xC000
    auto load_chunk = [&](int s, long g) {
        int tile = tile0 + (int)(g / KC) * GRID_P;
        int c = (int)(g % KC);
        int bm = (tile >> 5) * BM;
        int bn = (tile & 31) * BN;
        uint32_t base = sb + s * STG_B;
        int ko = c * BK;
        #pragma unroll
        for (int half = 0; half < 2; half++) {
            int k0 = ko + half * 64;
            #pragma unroll
            for (int i = 0; i < 4; i++) {
                int idx = tid + i * 256;
                int row = idx >> 3, c16 = idx & 7;
                uint32_t so = SWZ(row * 128 + c16 * 16);
                cpasync16(base + half * 0x4000 + so,
                          Ah + (size_t)(bm + row) * KK + k0 + c16 * 8);
            }
            #pragma unroll
            for (int i = 0; i < 4; i++) {
                int idx = tid + i * 256;
                int row = idx >> 3, c16 = idx & 7;
                uint32_t so = SWZ(row * 128 + c16 * 16);
                cpasync16(base + 0x8000 + half * 0x4000 + so,
                          Bh + (size_t)(bn + row) * KK + k0 + c16 * 8);
            }
        }
        asm volatile("cp.async.commit_group;" ::: "memory");
    };

    const int ar_ = lane & 15, ah_ = lane >> 4;
    const int nr_ = ((lane >> 4) << 3) + (lane & 7), nh_ = (lane >> 3) & 1;

    uint32_t af[2][4][4], bf[2][2][4];

    auto ldfrag = [&](int buf, uint32_t st, int ks) {
        uint32_t qa = st + (ks >> 2) * 0x4000;
        int k4 = ks & 3;
        #pragma unroll
        for (int mt = 0; mt < 4; mt++) {
            int row = wm * 64 + mt * 16 + ar_;
            ldsm4(af[buf][mt], qa + SWZ(row * 128 + k4 * 32 + ah_ * 16));
        }
        #pragma unroll
        for (int bt = 0; bt < 2; bt++) {
            int row = wn * 32 + bt * 16 + nr_;
            ldsm4(bf[buf][bt], qa + 0x8000 + SWZ(row * 128 + k4 * 32 + nh_ * 16));
        }
    };

    float acc[4][4][4];
    load_chunk(0, 0);
    if (doconv) conv_load((long)tile0 * KC);
    long g = 0;

    for (int j = 0; j < ntiles; j++) {
        int tile = tile0 + j * GRID_P;
        int bm = (tile >> 5) * BM;
        int bn = (tile & 31) * BN;

        #pragma unroll
        for (int a = 0; a < 4; a++)
            #pragma unroll
            for (int b = 0; b < 4; b++)
                #pragma unroll
                for (int q = 0; q < 4; q++) acc[a][b][q] = 0.f;

        for (int c = 0; c < KC; ++c, ++g) {
            asm volatile("cp.async.wait_group 0;" ::: "memory");
            __syncthreads();
            if (g + 1 < Gtot) load_chunk((int)((g + 1) & 1), g + 1);

            uint32_t st = sb + (int)(g & 1) * STG_B;
            ldfrag(0, st, 0);
            #pragma unroll
            for (int ks = 0; ks < 8; ks++) {
                int cur = ks & 1;
                if (ks < 7) ldfrag(cur ^ 1, st, ks + 1);
                #pragma unroll
                for (int mt = 0; mt < 4; mt++)
                    #pragma unroll
                    for (int bt = 0; bt < 2; bt++) {
                        mma16816(acc[mt][2 * bt],     af[cur][mt], bf[cur][bt][0], bf[cur][bt][1]);
                        mma16816(acc[mt][2 * bt + 1], af[cur][mt], bf[cur][bt][2], bf[cur][bt][3]);
                    }
            }

            // interleaved C' conversion: store oct for this (tile,chunk), prefetch next
            if (doconv) {
                long gq = (long)tile * KC + c;
                conv_store(gq);
                long nq = -1;
                if (c + 1 < KC) nq = gq + 1;
                else if (j + 1 < ntiles) nq = (long)(tile + GRID_P) * KC;
                if (nq >= 0) conv_load(nq);
            }
        }

        // epilogue (registers -> gmem; overlaps next tile's in-flight loads)
        const int r0 = bm + wm * 64 + (lane >> 2);
        const int c0 = bn + wn * 32 + (lane & 3) * 2;
        #pragma unroll
        for (int mt = 0; mt < 4; mt++) {
            #pragma unroll
            for (int nt = 0; nt < 4; nt++) {
                int row = r0 + mt * 16;
                int col = c0 + nt * 8;
                if (MODE == 0) {
                    __half2 v0 = __floats2half2_rn(acc[mt][nt][0], acc[mt][nt][1]);
                    __half2 v1 = __floats2half2_rn(acc[mt][nt][2], acc[mt][nt][3]);
                    *(__half2*)&g_bu_h[(size_t)row * NN + col]       = v0;
                    *(__half2*)&g_bu_h[(size_t)(row + 8) * NN + col] = v1;
                } else {
                    float2 dv = *(const float2*)&Dvec[col];
                    float2 x0 = *(const float2*)&x[(size_t)row * NN + col];
                    float2 x1 = *(const float2*)&x[(size_t)(row + 8) * NN + col];
                    float2 v0, v1;
                    v0.x = fmaf(x0.x, dv.x, acc[mt][nt][0]);
                    v0.y = fmaf(x0.y, dv.y, acc[mt][nt][1]);
                    v1.x = fmaf(x1.x, dv.x, acc[mt][nt][2]);
                    v1.y = fmaf(x1.y, dv.y, acc[mt][nt][3]);
                    *(float2*)&out[(size_t)row * NN + col]       = v0;
                    *(float2*)&out[(size_t)(row + 8) * NN + col] = v1;
                }
            }
        }
    }
}

// ---------------- scan (layout: [TT, 4096] = re|im), Bu in fp16 ----------------
__global__ void scan_chunks() {
    int h = blockIdx.x * blockDim.x + threadIdx.x;   // 0..HH-1
    int c = blockIdx.y;
    float lr = g_lam_re[h], li = g_lam_im[h];
    float hr = 0.f, hi = 0.f;
    size_t base = (size_t)c * CLEN * NN + h;
    #pragma unroll 8
    for (int t = 0; t < CLEN; t++) {
        float br = __half2float(g_bu_h[base + (size_t)t * NN]);
        float bi = __half2float(g_bu_h[base + (size_t)t * NN + HH]);
        float nr = fmaf(lr, hr, fmaf(-li, hi, br));
        float ni = fmaf(lr, hi, fmaf(li, hr, bi));
        hr = nr; hi = ni;
    }
    g_chunk_re[c * HH + h] = hr;
    g_chunk_im[c * HH + h] = hi;
}

__global__ void scan_carry() {
    int h = blockIdx.x * blockDim.x + threadIdx.x;
    float ar = g_lamL_re[h], ai = g_lamL_im[h];
    float cr = 0.f, ci = 0.f;
    for (int c = 0; c < NCHUNK; c++) {
        g_carry_re[c * HH + h] = cr;
        g_carry_im[c * HH + h] = ci;
        float pr = g_chunk_re[c * HH + h];
        float pi = g_chunk_im[c * HH + h];
        float nr = fmaf(ar, cr, fmaf(-ai, ci, pr));
        float ni = fmaf(ar, ci, fmaf(ai, cr, pi));
        cr = nr; ci = ni;
    }
}

__global__ void scan_final() {
    int h = blockIdx.x * blockDim.x + threadIdx.x;
    int c = blockIdx.y;
    float lr = g_lam_re[h], li = g_lam_im[h];
    float hr = g_carry_re[c * HH + h];
    float hi = g_carry_im[c * HH + h];
    size_t base = (size_t)c * CLEN * NN + h;
    #pragma unroll 4
    for (int t = 0; t < CLEN; t++) {
        size_t ir = base + (size_t)t * NN;
        float br = __half2float(g_bu_h[ir]);
        float bi = __half2float(g_bu_h[ir + HH]);
        float nr = fmaf(lr, hr, fmaf(-li, hi, br));
        float ni = fmaf(lr, hi, fmaf(li, hr, bi));
        hr = nr; hi = ni;
        g_h_h[ir]      = __float2half(hr);
        g_h_h[ir + HH] = __float2half(hi);
    }
}

// ---------------- launch ----------------
extern "C" void kernel_launch(void* const* d_in, const int* in_sizes, int n_in,
                              void* d_out, int out_size) {
    (void)in_sizes; (void)n_in; (void)out_size;
    const float* x         = (const float*)d_in[0];
    const float* nu_log    = (const float*)d_in[1];
    const float* theta_log = (const float*)d_in[2];
    const float* gamma_log = (const float*)d_in[3];
    const float* B_re      = (const float*)d_in[4];
    const float* B_im      = (const float*)d_in[5];
    const float* C_re      = (const float*)d_in[6];
    const float* C_im      = (const float*)d_in[7];
    const float* Dvec      = (const float*)d_in[8];
    float* out = (float*)d_out;

    cudaFuncSetAttribute(gemm_split<0>, cudaFuncAttributeMaxDynamicSharedMemorySize, SMEM_TOT);
    cudaFuncSetAttribute(gemm_split<1>, cudaFuncAttributeMaxDynamicSharedMemorySize, SMEM_TOT);

    init_params<<<(HH + 255) / 256, 256>>>(nu_log, theta_log, gamma_log);
    conv_xb<<<2 * (unsigned)NBREG, 256>>>(x, B_re, B_im);

    gemm_split<0><<<GRID_P, 256, SMEM_TOT>>>(x, Dvec, out, C_re, C_im);

    dim3 gs(HH / 256, NCHUNK);
    scan_chunks<<<gs, 256>>>();
    scan_carry<<<HH / 256, 256>>>();
    scan_final<<<gs, 256>>>();

    gemm_split<1><<<GRID_P, 256, SMEM_TOT>>>(x, Dvec, out, C_re, C_im);
}

// round 12
// speedup vs baseline: 1.0028x; 1.0028x over previous
#include <cuda_runtime.h>
#include <cuda_fp16.h>
#include <cstdint>
#include <math.h>

#define TT 4096      // SEQ_LEN (M for both GEMMs)
#define HH 2048      // D_HIDDEN
#define DM 4096      // D_MODEL
#define KK 4096      // K for both GEMMs
#define NN 4096      // N for both GEMMs
#define NCHUNK 64
#define CLEN 64

#define BM 128
#define BN 128
#define BK 128               // two 64-wide k-halves per chunk
#define KC (KK / BK)         // 32 chunks
#define NTILE ((TT / BM) * (NN / BN))   // 1024
#define GRID_P 148           // persistent CTAs
#define NTHR 128             // 4 warps
#define STG_B 0x10000        // 64KB per stage
#define SMEM_TOT (2 * STG_B) // 128KB

// ---------------- device scratch (no allocations allowed) ----------------
__device__ __half g_x_h[(size_t)TT * DM];     // x fp16
__device__ __half g_b_h[(size_t)NN * KK];     // [gB_re; gB_im] fp16
__device__ __half g_c_h[(size_t)NN * KK];     // [C_re | -C_im] fp16
__device__ __half g_h_h[(size_t)TT * KK];     // hidden (re|im) fp16
__device__ __half g_bu_h[(size_t)TT * NN];    // Bu (re|im) fp16
__device__ float g_lam_re[HH], g_lam_im[HH];
__device__ float g_lamL_re[HH], g_lamL_im[HH];
__device__ float g_gam[HH];
__device__ float g_chunk_re[NCHUNK * HH], g_chunk_im[NCHUNK * HH];
__device__ float g_carry_re[NCHUNK * HH], g_carry_im[NCHUNK * HH];

// ---------------- helpers ----------------
__device__ __forceinline__ uint32_t smem_u32(const void* p) {
    uint32_t a;
    asm("{ .reg .u64 t; cvta.to.shared.u64 t, %1; cvt.u32.u64 %0, t; }" : "=r"(a) : "l"(p));
    return a;
}
#define SWZ(o) ((o) ^ (((o) >> 3) & 0x70))

__device__ __forceinline__ void cpasync16(uint32_t dst, const void* src) {
    asm volatile("cp.async.cg.shared.global [%0], [%1], 16;" :: "r"(dst), "l"(src));
}
__device__ __forceinline__ void ldsm4(uint32_t* r, uint32_t addr) {
    asm volatile("ldmatrix.sync.aligned.m8n8.x4.shared.b16 {%0,%1,%2,%3}, [%4];"
                 : "=r"(r[0]), "=r"(r[1]), "=r"(r[2]), "=r"(r[3]) : "r"(addr));
}
__device__ __forceinline__ void mma16816(float* c, const uint32_t* a,
                                         uint32_t b0, uint32_t b1) {
    asm volatile(
        "mma.sync.aligned.m16n8k16.row.col.f32.f16.f16.f32 "
        "{%0,%1,%2,%3}, {%4,%5,%6,%7}, {%8,%9}, {%0,%1,%2,%3};"
        : "+f"(c[0]), "+f"(c[1]), "+f"(c[2]), "+f"(c[3])
        : "r"(a[0]), "r"(a[1]), "r"(a[2]), "r"(a[3]), "r"(b0), "r"(b1));
}

// pack 4 floats -> fp16 (uint2), packed cvt
__device__ __forceinline__ uint2 pack4s(const float4 v) {
    __half2 p0 = __floats2half2_rn(v.x, v.y);
    __half2 p1 = __floats2half2_rn(v.z, v.w);
    uint2 r;
    r.x = *(uint32_t*)&p0; r.y = *(uint32_t*)&p1;
    return r;
}

// ---------------- param precompute ----------------
__global__ void init_params(const float* __restrict__ nu_log,
                            const float* __restrict__ theta_log,
                            const float* __restrict__ gamma_log) {
    int h = blockIdx.x * blockDim.x + threadIdx.x;
    if (h >= HH) return;
    float nu = expf(nu_log[h]);
    float th = expf(theta_log[h]);
    float mag = expf(-nu);
    float lr = mag * cosf(th), li = mag * sinf(th);
    g_lam_re[h] = lr; g_lam_im[h] = li;
    g_gam[h] = expf(gamma_log[h]);
    float ar = 1.f, ai = 0.f;
    for (int i = 0; i < CLEN; i++) {
        float nr = ar * lr - ai * li;
        ai = ar * li + ai * lr; ar = nr;
    }
    g_lamL_re[h] = ar; g_lamL_im[h] = ai;
}

// ---------------- merged conversions (x | B' | C') ----------------
#define NBREG ((size_t)TT * DM / 8 / 256)   // 8192 blocks per region
__global__ void conv_all(const float* __restrict__ x,
                         const float* __restrict__ Bre, const float* __restrict__ Bim,
                         const float* __restrict__ Cre, const float* __restrict__ Cim) {
    unsigned bid = blockIdx.x;
    if (bid < NBREG) {
        size_t i = ((size_t)bid * 256 + threadIdx.x) * 8;
        float4 v0 = *(const float4*)(x + i);
        float4 v1 = *(const float4*)(x + i + 4);
        uint2 a = pack4s(v0), b = pack4s(v1);
        *(uint4*)(g_x_h + i) = make_uint4(a.x, a.y, b.x, b.y);
    } else if (bid < 2 * NBREG) {
        size_t i = ((size_t)(bid - NBREG) * 256 + threadIdx.x) * 8;
        unsigned row = (unsigned)(i >> 12);
        const float* src = (row < HH) ? (Bre + i) : (Bim + (i - (size_t)HH * DM));
        float g = g_gam[row < HH ? row : row - HH];
        float4 v0 = *(const float4*)src;
        float4 v1 = *(const float4*)(src + 4);
        v0.x *= g; v0.y *= g; v0.z *= g; v0.w *= g;
        v1.x *= g; v1.y *= g; v1.z *= g; v1.w *= g;
        uint2 a = pack4s(v0), b = pack4s(v1);
        *(uint4*)(g_b_h + i) = make_uint4(a.x, a.y, b.x, b.y);
    } else {
        size_t i = ((size_t)(bid - 2 * NBREG) * 256 + threadIdx.x) * 8;
        unsigned d = (unsigned)(i >> 12);
        unsigned j = (unsigned)(i & (KK - 1));
        float4 v0, v1;
        if (j < HH) {
            v0 = *(const float4*)(Cre + (size_t)d * HH + j);
            v1 = *(const float4*)(Cre + (size_t)d * HH + j + 4);
        } else {
            v0 = *(const float4*)(Cim + (size_t)d * HH + (j - HH));
            v1 = *(const float4*)(Cim + (size_t)d * HH + (j - HH) + 4);
            v0.x = -v0.x; v0.y = -v0.y; v0.z = -v0.z; v0.w = -v0.w;
            v1.x = -v1.x; v1.y = -v1.y; v1.z = -v1.z; v1.w = -v1.w;
        }
        uint2 a = pack4s(v0), b = pack4s(v1);
        *(uint4*)(g_c_h + i) = make_uint4(a.x, a.y, b.x, b.y);
    }
}

// ---------------- persistent fp16 GEMM, 128x128 tiles, 4 warps of 64x64 ----------------
// MODE 0: g_bu_h = fp16( x @ B'^T )
// MODE 1: out    = h @ C'^T + x*D   (fp32 out)
template <int MODE>
__global__ __launch_bounds__(NTHR, 1) void gemm_split(
    const float* __restrict__ x, const float* __restrict__ Dvec, float* __restrict__ out)
{
    extern __shared__ char smem[];
    const uint32_t sb = smem_u32(smem);
    const __half *Ah, *Bh;
    if (MODE == 0) { Ah = g_x_h; Bh = g_b_h; }
    else           { Ah = g_h_h; Bh = g_c_h; }

    const int tid = threadIdx.x, lane = tid & 31, wid = tid >> 5;
    const int wm = wid & 1, wn = wid >> 1;           // 2 x 2 warp grid -> 64x64 warp tile
    const int tile0 = blockIdx.x;
    const int ntiles = (NTILE - 1 - tile0) / GRID_P + 1;
    const long Gtot = (long)ntiles * KC;

    // stage layout (64KB): A half0 0x0000, A half1 0x4000, B half0 0x8000, B half1 0xC000
    auto load_chunk = [&](int s, long g) {
        int tile = tile0 + (int)(g / KC) * GRID_P;
        int c = (int)(g % KC);
        int bm = (tile >> 5) * BM;
        int bn = (tile & 31) * BN;
        uint32_t base = sb + s * STG_B;
        int ko = c * BK;
        #pragma unroll
        for (int half = 0; half < 2; half++) {
            int k0 = ko + half * 64;
            #pragma unroll
            for (int i = 0; i < 8; i++) {
                int idx = tid + i * NTHR;
                int row = idx >> 3, c16 = idx & 7;
                uint32_t so = SWZ(row * 128 + c16 * 16);
                cpasync16(base + half * 0x4000 + so,
                          Ah + (size_t)(bm + row) * KK + k0 + c16 * 8);
            }
            #pragma unroll
            for (int i = 0; i < 8; i++) {
                int idx = tid + i * NTHR;
                int row = idx >> 3, c16 = idx & 7;
                uint32_t so = SWZ(row * 128 + c16 * 16);
                cpasync16(base + 0x8000 + half * 0x4000 + so,
                          Bh + (size_t)(bn + row) * KK + k0 + c16 * 8);
            }
        }
        asm volatile("cp.async.commit_group;" ::: "memory");
    };

    const int ar_ = lane & 15, ah_ = lane >> 4;
    const int nr_ = ((lane >> 4) << 3) + (lane & 7), nh_ = (lane >> 3) & 1;

    uint32_t af[2][4][4], bf[2][4][4];

    auto ldfrag = [&](int buf, uint32_t st, int ks) {
        uint32_t qa = st + (ks >> 2) * 0x4000;
        int k4 = ks & 3;
        #pragma unroll
        for (int mt = 0; mt < 4; mt++) {
            int row = wm * 64 + mt * 16 + ar_;
            ldsm4(af[buf][mt], qa + SWZ(row * 128 + k4 * 32 + ah_ * 16));
        }
        #pragma unroll
        for (int bt = 0; bt < 4; bt++) {
            int row = wn * 64 + bt * 16 + nr_;
            ldsm4(bf[buf][bt], qa + 0x8000 + SWZ(row * 128 + k4 * 32 + nh_ * 16));
        }
    };

    float acc[4][8][4];
    load_chunk(0, 0);
    long g = 0;

    for (int j = 0; j < ntiles; j++) {
        int tile = tile0 + j * GRID_P;
        int bm = (tile >> 5) * BM;
        int bn = (tile & 31) * BN;

        #pragma unroll
        for (int a = 0; a < 4; a++)
            #pragma unroll
            for (int b = 0; b < 8; b++)
                #pragma unroll
                for (int q = 0; q < 4; q++) acc[a][b][q] = 0.f;

        for (int c = 0; c < KC; ++c, ++g) {
            asm volatile("cp.async.wait_group 0;" ::: "memory");
            __syncthreads();
            if (g + 1 < Gtot) load_chunk((int)((g + 1) & 1), g + 1);

            uint32_t st = sb + (int)(g & 1) * STG_B;
            ldfrag(0, st, 0);
            #pragma unroll
            for (int ks = 0; ks < 8; ks++) {
                int cur = ks & 1;
                if (ks < 7) ldfrag(cur ^ 1, st, ks + 1);
                #pragma unroll
                for (int mt = 0; mt < 4; mt++)
                    #pragma unroll
                    for (int bt = 0; bt < 4; bt++) {
                        mma16816(acc[mt][2 * bt],     af[cur][mt], bf[cur][bt][0], bf[cur][bt][1]);
                        mma16816(acc[mt][2 * bt + 1], af[cur][mt], bf[cur][bt][2], bf[cur][bt][3]);
                    }
            }
        }

        // epilogue (registers -> gmem; overlaps next tile's in-flight loads)
        const int r0 = bm + wm * 64 + (lane >> 2);
        const int c0 = bn + wn * 64 + (lane & 3) * 2;
        #pragma unroll
        for (int mt = 0; mt < 4; mt++) {
            #pragma unroll
            for (int nt = 0; nt < 8; nt++) {
                int row = r0 + mt * 16;
                int col = c0 + nt * 8;
                if (MODE == 0) {
                    __half2 v0 = __floats2half2_rn(acc[mt][nt][0], acc[mt][nt][1]);
                    __half2 v1 = __floats2half2_rn(acc[mt][nt][2], acc[mt][nt][3]);
                    *(__half2*)&g_bu_h[(size_t)row * NN + col]       = v0;
                    *(__half2*)&g_bu_h[(size_t)(row + 8) * NN + col] = v1;
                } else {
                    float2 dv = *(const float2*)&Dvec[col];
                    float2 x0 = *(const float2*)&x[(size_t)row * NN + col];
                    float2 x1 = *(const float2*)&x[(size_t)(row + 8) * NN + col];
                    float2 v0, v1;
                    v0.x = fmaf(x0.x, dv.x, acc[mt][nt][0]);
                    v0.y = fmaf(x0.y, dv.y, acc[mt][nt][1]);
                    v1.x = fmaf(x1.x, dv.x, acc[mt][nt][2]);
                    v1.y = fmaf(x1.y, dv.y, acc[mt][nt][3]);
                    *(float2*)&out[(size_t)row * NN + col]       = v0;
                    *(float2*)&out[(size_t)(row + 8) * NN + col] = v1;
                }
            }
        }
    }
}

// ---------------- scan (layout: [TT, 4096] = re|im), 2 channels/thread ----------------
__global__ void scan_chunks() {
    int idx = blockIdx.x * blockDim.x + threadIdx.x;  // 0..HH/2-1
    int h = idx * 2;
    int c = blockIdx.y;
    float2 lr = *(const float2*)&g_lam_re[h];
    float2 li = *(const float2*)&g_lam_im[h];
    float hr0 = 0.f, hi0 = 0.f, hr1 = 0.f, hi1 = 0.f;
    size_t base = (size_t)c * CLEN * NN + h;
    #pragma unroll 4
    for (int t = 0; t < CLEN; t++) {
        __half2 br = *(const __half2*)&g_bu_h[base + (size_t)t * NN];
        __half2 bi = *(const __half2*)&g_bu_h[base + (size_t)t * NN + HH];
        float2 brf = __half22float2(br), bif = __half22float2(bi);
        float nr0 = fmaf(lr.x, hr0, fmaf(-li.x, hi0, brf.x));
        float ni0 = fmaf(lr.x, hi0, fmaf(li.x, hr0, bif.x));
        float nr1 = fmaf(lr.y, hr1, fmaf(-li.y, hi1, brf.y));
        float ni1 = fmaf(lr.y, hi1, fmaf(li.y, hr1, bif.y));
        hr0 = nr0; hi0 = ni0; hr1 = nr1; hi1 = ni1;
    }
    *(float2*)&g_chunk_re[c * HH + h] = make_float2(hr0, hr1);
    *(float2*)&g_chunk_im[c * HH + h] = make_float2(hi0, hi1);
}

__global__ void scan_carry() {
    int h = blockIdx.x * blockDim.x + threadIdx.x;
    float ar = g_lamL_re[h], ai = g_lamL_im[h];
    float cr = 0.f, ci = 0.f;
    for (int c = 0; c < NCHUNK; c++) {
        g_carry_re[c * HH + h] = cr;
        g_carry_im[c * HH + h] = ci;
        float pr = g_chunk_re[c * HH + h];
        float pi = g_chunk_im[c * HH + h];
        float nr = fmaf(ar, cr, fmaf(-ai, ci, pr));
        float ni = fmaf(ar, ci, fmaf(ai, cr, pi));
        cr = nr; ci = ni;
    }
}

__global__ void scan_final() {
    int idx = blockIdx.x * blockDim.x + threadIdx.x;  // 0..HH/2-1
    int h = idx * 2;
    int c = blockIdx.y;
    float2 lr = *(const float2*)&g_lam_re[h];
    float2 li = *(const float2*)&g_lam_im[h];
    float2 cr = *(const float2*)&g_carry_re[c * HH + h];
    float2 ci = *(const float2*)&g_carry_im[c * HH + h];
    float hr0 = cr.x, hi0 = ci.x, hr1 = cr.y, hi1 = ci.y;
    size_t base = (size_t)c * CLEN * NN + h;
    #pragma unroll 4
    for (int t = 0; t < CLEN; t++) {
        size_t ir = base + (size_t)t * NN;
        __half2 br = *(const __half2*)&g_bu_h[ir];
        __half2 bi = *(const __half2*)&g_bu_h[ir + HH];
        float2 brf = __half22float2(br), bif = __half22float2(bi);
        float nr0 = fmaf(lr.x, hr0, fmaf(-li.x, hi0, brf.x));
        float ni0 = fmaf(lr.x, hi0, fmaf(li.x, hr0, bif.x));
        float nr1 = fmaf(lr.y, hr1, fmaf(-li.y, hi1, brf.y));
        float ni1 = fmaf(lr.y, hi1, fmaf(li.y, hr1, bif.y));
        hr0 = nr0; hi0 = ni0; hr1 = nr1; hi1 = ni1;
        *(__half2*)&g_h_h[ir]      = __floats2half2_rn(hr0, hr1);
        *(__half2*)&g_h_h[ir + HH] = __floats2half2_rn(hi0, hi1);
    }
}

// ---------------- launch ----------------
extern "C" void kernel_launch(void* const* d_in, const int* in_sizes, int n_in,
                              void* d_out, int out_size) {
    (void)in_sizes; (void)n_in; (void)out_size;
    const float* x         = (const float*)d_in[0];
    const float* nu_log    = (const float*)d_in[1];
    const float* theta_log = (const float*)d_in[2];
    const float* gamma_log = (const float*)d_in[3];
    const float* B_re      = (const float*)d_in[4];
    const float* B_im      = (const float*)d_in[5];
    const float* C_re      = (const float*)d_in[6];
    const float* C_im      = (const float*)d_in[7];
    const float* Dvec      = (const float*)d_in[8];
    float* out = (float*)d_out;

    cudaFuncSetAttribute(gemm_split<0>, cudaFuncAttributeMaxDynamicSharedMemorySize, SMEM_TOT);
    cudaFuncSetAttribute(gemm_split<1>, cudaFuncAttributeMaxDynamicSharedMemorySize, SMEM_TOT);

    init_params<<<(HH + 255) / 256, 256>>>(nu_log, theta_log, gamma_log);
    conv_all<<<3 * (unsigned)NBREG, 256>>>(x, B_re, B_im, C_re, C_im);

    gemm_split<0><<<GRID_P, NTHR, SMEM_TOT>>>(x, Dvec, out);

    dim3 gs(HH / 2 / 256, NCHUNK);
    scan_chunks<<<gs, 256>>>();
    scan_carry<<<HH / 256, 256>>>();
    scan_final<<<gs, 256>>>();

    gemm_split<1><<<GRID_P, NTHR, SMEM_TOT>>>(x, Dvec, out);
}

// round 13
// speedup vs baseline: 1.0102x; 1.0074x over previous
#include <cuda_runtime.h>
#include <cuda_fp16.h>
#include <cstdint>
#include <math.h>

#define TT 4096      // SEQ_LEN (M for both GEMMs)
#define HH 2048      // D_HIDDEN
#define DM 4096      // D_MODEL
#define KK 4096      // K for both GEMMs
#define NN 4096      // N for both GEMMs
#define NCHUNK 64
#define CLEN 64

#define BM 128
#define BN 128
#define BK 128               // two 64-wide k-halves per chunk
#define KC (KK / BK)         // 32 chunks
#define NTILE ((TT / BM) * (NN / BN))   // 1024
#define GRID_P 148           // persistent CTAs
#define STG_B 0x10000        // 64KB per stage
#define SMEM_TOT (2 * STG_B) // 128KB

// ---------------- device scratch (no allocations allowed) ----------------
__device__ __half g_x_h[(size_t)TT * DM];     // x fp16
__device__ __half g_b_h[(size_t)NN * KK];     // [gB_re; gB_im] fp16
__device__ __half g_c_h[(size_t)NN * KK];     // [C_re | -C_im] fp16
__device__ __half g_h_h[(size_t)TT * KK];     // hidden (re|im) fp16
__device__ __half g_bu_h[(size_t)TT * NN];    // Bu (re|im) fp16
__device__ float g_lam_re[HH], g_lam_im[HH];
__device__ float g_lamL_re[HH], g_lamL_im[HH];
__device__ float g_gam[HH];
__device__ float g_chunk_re[NCHUNK * HH], g_chunk_im[NCHUNK * HH];
__device__ float g_carry_re[NCHUNK * HH], g_carry_im[NCHUNK * HH];

// ---------------- helpers ----------------
__device__ __forceinline__ uint32_t smem_u32(const void* p) {
    uint32_t a;
    asm("{ .reg .u64 t; cvta.to.shared.u64 t, %1; cvt.u32.u64 %0, t; }" : "=r"(a) : "l"(p));
    return a;
}
#define SWZ(o) ((o) ^ (((o) >> 3) & 0x70))

__device__ __forceinline__ void cpasync16(uint32_t dst, const void* src) {
    asm volatile("cp.async.cg.shared.global [%0], [%1], 16;" :: "r"(dst), "l"(src));
}
__device__ __forceinline__ void ldsm4(uint32_t* r, uint32_t addr) {
    asm volatile("ldmatrix.sync.aligned.m8n8.x4.shared.b16 {%0,%1,%2,%3}, [%4];"
                 : "=r"(r[0]), "=r"(r[1]), "=r"(r[2]), "=r"(r[3]) : "r"(addr));
}
__device__ __forceinline__ void mma16816(float* c, const uint32_t* a,
                                         uint32_t b0, uint32_t b1) {
    asm volatile(
        "mma.sync.aligned.m16n8k16.row.col.f32.f16.f16.f32 "
        "{%0,%1,%2,%3}, {%4,%5,%6,%7}, {%8,%9}, {%0,%1,%2,%3};"
        : "+f"(c[0]), "+f"(c[1]), "+f"(c[2]), "+f"(c[3])
        : "r"(a[0]), "r"(a[1]), "r"(a[2]), "r"(a[3]), "r"(b0), "r"(b1));
}

// pack 4 floats -> fp16 (uint2), packed cvt
__device__ __forceinline__ uint2 pack4s(const float4 v) {
    __half2 p0 = __floats2half2_rn(v.x, v.y);
    __half2 p1 = __floats2half2_rn(v.z, v.w);
    uint2 r;
    r.x = *(uint32_t*)&p0; r.y = *(uint32_t*)&p1;
    return r;
}

// ---------------- param precompute ----------------
__global__ void init_params(const float* __restrict__ nu_log,
                            const float* __restrict__ theta_log,
                            const float* __restrict__ gamma_log) {
    int h = blockIdx.x * blockDim.x + threadIdx.x;
    if (h >= HH) return;
    float nu = expf(nu_log[h]);
    float th = expf(theta_log[h]);
    float mag = expf(-nu);
    float lr = mag * cosf(th), li = mag * sinf(th);
    g_lam_re[h] = lr; g_lam_im[h] = li;
    g_gam[h] = expf(gamma_log[h]);
    float ar = 1.f, ai = 0.f;
    for (int i = 0; i < CLEN; i++) {
        float nr = ar * lr - ai * li;
        ai = ar * li + ai * lr; ar = nr;
    }
    g_lamL_re[h] = ar; g_lamL_im[h] = ai;
}

// ---------------- merged conversions (x | B' | C'), 16 elems/thread ----------------
#define NBREG ((size_t)TT * DM / 16 / 256)   // 4096 blocks per region
__global__ void conv_all(const float* __restrict__ x,
                         const float* __restrict__ Bre, const float* __restrict__ Bim,
                         const float* __restrict__ Cre, const float* __restrict__ Cim) {
    unsigned bid = blockIdx.x;
    if (bid < NBREG) {
        size_t i = ((size_t)bid * 256 + threadIdx.x) * 16;
        float4 v0 = *(const float4*)(x + i);
        float4 v1 = *(const float4*)(x + i + 4);
        float4 v2 = *(const float4*)(x + i + 8);
        float4 v3 = *(const float4*)(x + i + 12);
        uint2 a = pack4s(v0), b = pack4s(v1), c = pack4s(v2), d = pack4s(v3);
        *(uint4*)(g_x_h + i)     = make_uint4(a.x, a.y, b.x, b.y);
        *(uint4*)(g_x_h + i + 8) = make_uint4(c.x, c.y, d.x, d.y);
    } else if (bid < 2 * NBREG) {
        size_t i = ((size_t)(bid - NBREG) * 256 + threadIdx.x) * 16;
        unsigned row = (unsigned)(i >> 12);                // constant across 16 elems
        const float* src = (row < HH) ? (Bre + i) : (Bim + (i - (size_t)HH * DM));
        float g = g_gam[row < HH ? row : row - HH];
        float4 v0 = *(const float4*)src;
        float4 v1 = *(const float4*)(src + 4);
        float4 v2 = *(const float4*)(src + 8);
        float4 v3 = *(const float4*)(src + 12);
        v0.x *= g; v0.y *= g; v0.z *= g; v0.w *= g;
        v1.x *= g; v1.y *= g; v1.z *= g; v1.w *= g;
        v2.x *= g; v2.y *= g; v2.z *= g; v2.w *= g;
        v3.x *= g; v3.y *= g; v3.z *= g; v3.w *= g;
        uint2 a = pack4s(v0), b = pack4s(v1), c = pack4s(v2), d = pack4s(v3);
        *(uint4*)(g_b_h + i)     = make_uint4(a.x, a.y, b.x, b.y);
        *(uint4*)(g_b_h + i + 8) = make_uint4(c.x, c.y, d.x, d.y);
    } else {
        size_t i = ((size_t)(bid - 2 * NBREG) * 256 + threadIdx.x) * 16;
        unsigned d_ = (unsigned)(i >> 12);
        unsigned j = (unsigned)(i & (KK - 1));             // 16-aligned; j<HH constant
        const float* src = (j < HH) ? (Cre + (size_t)d_ * HH + j)
                                    : (Cim + (size_t)d_ * HH + (j - HH));
        float4 v0 = *(const float4*)src;
        float4 v1 = *(const float4*)(src + 4);
        float4 v2 = *(const float4*)(src + 8);
        float4 v3 = *(const float4*)(src + 12);
        if (j >= HH) {
            v0.x = -v0.x; v0.y = -v0.y; v0.z = -v0.z; v0.w = -v0.w;
            v1.x = -v1.x; v1.y = -v1.y; v1.z = -v1.z; v1.w = -v1.w;
            v2.x = -v2.x; v2.y = -v2.y; v2.z = -v2.z; v2.w = -v2.w;
            v3.x = -v3.x; v3.y = -v3.y; v3.z = -v3.z; v3.w = -v3.w;
        }
        uint2 a = pack4s(v0), b = pack4s(v1), c = pack4s(v2), d = pack4s(v3);
        *(uint4*)(g_c_h + i)     = make_uint4(a.x, a.y, b.x, b.y);
        *(uint4*)(g_c_h + i + 8) = make_uint4(c.x, c.y, d.x, d.y);
    }
}

// ---------------- persistent fp16 GEMM, 128x128 tiles, BK=128 ----------------
// MODE 0: g_bu_h = fp16( x @ B'^T )
// MODE 1: out    = h @ C'^T + x*D   (fp32 out)
template <int MODE>
__global__ __launch_bounds__(256, 1) void gemm_split(
    const float* __restrict__ x, const float* __restrict__ Dvec, float* __restrict__ out)
{
    extern __shared__ char smem[];
    const uint32_t sb = smem_u32(smem);
    const __half *Ah, *Bh;
    if (MODE == 0) { Ah = g_x_h; Bh = g_b_h; }
    else           { Ah = g_h_h; Bh = g_c_h; }

    const int tid = threadIdx.x, lane = tid & 31, wid = tid >> 5;
    const int wm = wid & 1, wn = wid >> 1;           // 2 x 4 warp grid -> 64x32 warp tile
    const int tile0 = blockIdx.x;
    const int ntiles = (NTILE - 1 - tile0) / GRID_P + 1;
    const long Gtot = (long)ntiles * KC;

    // stage layout (64KB): A half0 0x0000, A half1 0x4000, B half0 0x8000, B half1 0xC000
    auto load_chunk = [&](int s, long g) {
        int tile = tile0 + (int)(g / KC) * GRID_P;
        int c = (int)(g % KC);
        int bm = (tile >> 5) * BM;
        int bn = (tile & 31) * BN;
        uint32_t base = sb + s * STG_B;
        int ko = c * BK;
        #pragma unroll
        for (int half = 0; half < 2; half++) {
            int k0 = ko + half * 64;
            #pragma unroll
            for (int i = 0; i < 4; i++) {
                int idx = tid + i * 256;
                int row = idx >> 3, c16 = idx & 7;
                uint32_t so = SWZ(row * 128 + c16 * 16);
                cpasync16(base + half * 0x4000 + so,
                          Ah + (size_t)(bm + row) * KK + k0 + c16 * 8);
            }
            #pragma unroll
            for (int i = 0; i < 4; i++) {
                int idx = tid + i * 256;
                int row = idx >> 3, c16 = idx & 7;
                uint32_t so = SWZ(row * 128 + c16 * 16);
                cpasync16(base + 0x8000 + half * 0x4000 + so,
                          Bh + (size_t)(bn + row) * KK + k0 + c16 * 8);
            }
        }
        asm volatile("cp.async.commit_group;" ::: "memory");
    };

    const int ar_ = lane & 15, ah_ = lane >> 4;
    const int nr_ = ((lane >> 4) << 3) + (lane & 7), nh_ = (lane >> 3) & 1;

    uint32_t af[2][4][4], bf[2][2][4];

    auto ldfrag = [&](int buf, uint32_t st, int ks) {
        uint32_t qa = st + (ks >> 2) * 0x4000;
        int k4 = ks & 3;
        #pragma unroll
        for (int mt = 0; mt < 4; mt++) {
            int row = wm * 64 + mt * 16 + ar_;
            ldsm4(af[buf][mt], qa + SWZ(row * 128 + k4 * 32 + ah_ * 16));
        }
        #pragma unroll
        for (int bt = 0; bt < 2; bt++) {
            int row = wn * 32 + bt * 16 + nr_;
            ldsm4(bf[buf][bt], qa + 0x8000 + SWZ(row * 128 + k4 * 32 + nh_ * 16));
        }
    };

    float acc[4][4][4];
    load_chunk(0, 0);
    long g = 0;

    for (int j = 0; j < ntiles; j++) {
        int tile = tile0 + j * GRID_P;
        int bm = (tile >> 5) * BM;
        int bn = (tile & 31) * BN;

        #pragma unroll
        for (int a = 0; a < 4; a++)
            #pragma unroll
            for (int b = 0; b < 4; b++)
                #pragma unroll
                for (int q = 0; q < 4; q++) acc[a][b][q] = 0.f;

        for (int c = 0; c < KC; ++c, ++g) {
            asm volatile("cp.async.wait_group 0;" ::: "memory");
            __syncthreads();
            if (g + 1 < Gtot) load_chunk((int)((g + 1) & 1), g + 1);

            uint32_t st = sb + (int)(g & 1) * STG_B;
            ldfrag(0, st, 0);
            #pragma unroll
            for (int ks = 0; ks < 8; ks++) {
                int cur = ks & 1;
                if (ks < 7) ldfrag(cur ^ 1, st, ks + 1);
                #pragma unroll
                for (int mt = 0; mt < 4; mt++)
                    #pragma unroll
                    for (int bt = 0; bt < 2; bt++) {
                        mma16816(acc[mt][2 * bt],     af[cur][mt], bf[cur][bt][0], bf[cur][bt][1]);
                        mma16816(acc[mt][2 * bt + 1], af[cur][mt], bf[cur][bt][2], bf[cur][bt][3]);
                    }
            }
        }

        // epilogue (registers -> gmem; overlaps next tile's in-flight loads)
        const int r0 = bm + wm * 64 + (lane >> 2);
        const int c0 = bn + wn * 32 + (lane & 3) * 2;
        #pragma unroll
        for (int mt = 0; mt < 4; mt++) {
            #pragma unroll
            for (int nt = 0; nt < 4; nt++) {
                int row = r0 + mt * 16;
                int col = c0 + nt * 8;
                if (MODE == 0) {
                    __half2 v0 = __floats2half2_rn(acc[mt][nt][0], acc[mt][nt][1]);
                    __half2 v1 = __floats2half2_rn(acc[mt][nt][2], acc[mt][nt][3]);
                    *(__half2*)&g_bu_h[(size_t)row * NN + col]       = v0;
                    *(__half2*)&g_bu_h[(size_t)(row + 8) * NN + col] = v1;
                } else {
                    float2 dv = *(const float2*)&Dvec[col];
                    float2 x0 = *(const float2*)&x[(size_t)row * NN + col];
                    float2 x1 = *(const float2*)&x[(size_t)(row + 8) * NN + col];
                    float2 v0, v1;
                    v0.x = fmaf(x0.x, dv.x, acc[mt][nt][0]);
                    v0.y = fmaf(x0.y, dv.y, acc[mt][nt][1]);
                    v1.x = fmaf(x1.x, dv.x, acc[mt][nt][2]);
                    v1.y = fmaf(x1.y, dv.y, acc[mt][nt][3]);
                    *(float2*)&out[(size_t)row * NN + col]       = v0;
                    *(float2*)&out[(size_t)(row + 8) * NN + col] = v1;
                }
            }
        }
    }
}

// ---------------- scan (layout: [TT, 4096] = re|im), Bu in fp16 ----------------
__global__ void scan_chunks() {
    int h = blockIdx.x * blockDim.x + threadIdx.x;   // 0..HH-1
    int c = blockIdx.y;
    float lr = g_lam_re[h], li = g_lam_im[h];
    float hr = 0.f, hi = 0.f;
    size_t base = (size_t)c * CLEN * NN + h;
    #pragma unroll 8
    for (int t = 0; t < CLEN; t++) {
        float br = __half2float(g_bu_h[base + (size_t)t * NN]);
        float bi = __half2float(g_bu_h[base + (size_t)t * NN + HH]);
        float nr = fmaf(lr, hr, fmaf(-li, hi, br));
        float ni = fmaf(lr, hi, fmaf(li, hr, bi));
        hr = nr; hi = ni;
    }
    g_chunk_re[c * HH + h] = hr;
    g_chunk_im[c * HH + h] = hi;
}

__global__ void scan_carry() {
    int h = blockIdx.x * blockDim.x + threadIdx.x;
    float ar = g_lamL_re[h], ai = g_lamL_im[h];
    float cr = 0.f, ci = 0.f;
    for (int c = 0; c < NCHUNK; c++) {
        g_carry_re[c * HH + h] = cr;
        g_carry_im[c * HH + h] = ci;
        float pr = g_chunk_re[c * HH + h];
        float pi = g_chunk_im[c * HH + h];
        float nr = fmaf(ar, cr, fmaf(-ai, ci, pr));
        float ni = fmaf(ar, ci, fmaf(ai, cr, pi));
        cr = nr; ci = ni;
    }
}

__global__ void scan_final() {
    int h = blockIdx.x * blockDim.x + threadIdx.x;
    int c = blockIdx.y;
    float lr = g_lam_re[h], li = g_lam_im[h];
    float hr = g_carry_re[c * HH + h];
    float hi = g_carry_im[c * HH + h];
    size_t base = (size_t)c * CLEN * NN + h;
    #pragma unroll 4
    for (int t = 0; t < CLEN; t++) {
        size_t ir = base + (size_t)t * NN;
        float br = __half2float(g_bu_h[ir]);
        float bi = __half2float(g_bu_h[ir + HH]);
        float nr = fmaf(lr, hr, fmaf(-li, hi, br));
        float ni = fmaf(lr, hi, fmaf(li, hr, bi));
        hr = nr; hi = ni;
        g_h_h[ir]      = __float2half(hr);
        g_h_h[ir + HH] = __float2half(hi);
    }
}

// ---------------- launch ----------------
extern "C" void kernel_launch(void* const* d_in, const int* in_sizes, int n_in,
                              void* d_out, int out_size) {
    (void)in_sizes; (void)n_in; (void)out_size;
    const float* x         = (const float*)d_in[0];
    const float* nu_log    = (const float*)d_in[1];
    const float* theta_log = (const float*)d_in[2];
    const float* gamma_log = (const float*)d_in[3];
    const float* B_re      = (const float*)d_in[4];
    const float* B_im      = (const float*)d_in[5];
    const float* C_re      = (const float*)d_in[6];
    const float* C_im      = (const float*)d_in[7];
    const float* Dvec      = (const float*)d_in[8];
    float* out = (float*)d_out;

    cudaFuncSetAttribute(gemm_split<0>, cudaFuncAttributeMaxDynamicSharedMemorySize, SMEM_TOT);
    cudaFuncSetAttribute(gemm_split<1>, cudaFuncAttributeMaxDynamicSharedMemorySize, SMEM_TOT);

    init_params<<<(HH + 255) / 256, 256>>>(nu_log, theta_log, gamma_log);
    conv_all<<<3 * (unsigned)NBREG, 256>>>(x, B_re, B_im, C_re, C_im);

    gemm_split<0><<<GRID_P, 256, SMEM_TOT>>>(x, Dvec, out);

    dim3 gs(HH / 256, NCHUNK);
    scan_chunks<<<gs, 256>>>();
    scan_carry<<<HH / 256, 256>>>();
    scan_final<<<gs, 256>>>();

    gemm_split<1><<<GRID_P, 256, SMEM_TOT>>>(x, Dvec, out);
}